// round 3
// baseline (speedup 1.0000x reference)
#include <cuda_runtime.h>

#define NROWS 65536   // N_TOKENS * BATCH
#define FDIM  256     // HW
#define MDIM  1024    // MEM_DIM

// ---------------- scratch (static device globals; no allocation) ----------------
__device__ float g_qc[NROWS * FDIM];            // centered q, row-major [N, F]   (64 MB)
__device__ float g_qm[NROWS];
__device__ float g_qv[NROWS];
__device__ float g_kcT[FDIM * MDIM];            // centered k, TRANSPOSED [F, M]  (1 MB)
__device__ float g_vmat[MDIM * FDIM];           // v, row-major [M, F]            (1 MB)
__device__ float g_km[MDIM];
__device__ float g_kv[MDIM];
__device__ float g_S[(size_t)NROWS * MDIM];     // ssim / att scores [N, M]       (256 MB)

// ---------------- packed f32x2 helpers (full-rate FP32 on sm_103a) --------------
__device__ __forceinline__ unsigned long long pk2(float lo, float hi) {
    unsigned long long r;
    asm("mov.b64 %0, {%1, %2};" : "=l"(r) : "f"(lo), "f"(hi));
    return r;
}
__device__ __forceinline__ void fma2(unsigned long long& d, unsigned long long a,
                                     unsigned long long b) {
    asm("fma.rn.f32x2 %0, %1, %2, %0;" : "+l"(d) : "l"(a), "l"(b));
}
__device__ __forceinline__ float2 upk2(unsigned long long v) {
    float2 r;
    asm("mov.b64 {%0, %1}, %2;" : "=f"(r.x), "=f"(r.y) : "l"(v));
    return r;
}

// =================================================================================
// rowgemm: C[64 x 256] = A_tile @ W^T   (W is [256,256] row-major, C[n,j]=sum A[n,f]W[j,f])
// MODE 0: q     -> row stats (mean/var), write centered rows to g_qc, g_qm/g_qv
// MODE 1: k     -> row stats, write centered TRANSPOSED to g_kcT, g_km/g_kv
// MODE 2: v     -> plain row-major store to g_vmat
// 256 threads, micro-tile 8x8 per thread (rows: tr*4+i / +32, cols: tc*4+j / +128)
// =================================================================================
template <int MODE>
__global__ __launch_bounds__(256, 2) void rowgemm_kernel(const float* __restrict__ A,
                                                         const float* __restrict__ W) {
    __shared__ float As[16][68];    // As[kk][row]
    __shared__ float Bs[16][260];   // Bs[kk][col]

    const int tid = threadIdx.x;
    const int n0  = blockIdx.x * 64;
    const int tr  = tid >> 5;   // 0..7   (warp id; all lanes of a warp share rows)
    const int tc  = tid & 31;   // 0..31

    unsigned long long accp[8][4];
#pragma unroll
    for (int i = 0; i < 8; i++)
#pragma unroll
        for (int j = 0; j < 4; j++) accp[i][j] = 0ull;

    for (int k0 = 0; k0 < 256; k0 += 16) {
        {   // A tile 64x16 (transpose into smem)
            int r = tid >> 2;
            int c = (tid & 3) << 2;
            float4 v = *(const float4*)&A[(n0 + r) * 256 + k0 + c];
            As[c + 0][r] = v.x; As[c + 1][r] = v.y; As[c + 2][r] = v.z; As[c + 3][r] = v.w;
        }
#pragma unroll
        for (int it = 0; it < 4; it++) {   // W tile 256x16 (transpose into smem)
            int fid = tid + (it << 8);
            int j = fid >> 2;
            int c = (fid & 3) << 2;
            float4 v = *(const float4*)&W[j * 256 + k0 + c];
            Bs[c + 0][j] = v.x; Bs[c + 1][j] = v.y; Bs[c + 2][j] = v.z; Bs[c + 3][j] = v.w;
        }
        __syncthreads();
#pragma unroll
        for (int kk = 0; kk < 16; kk++) {
            float4 a0 = *(const float4*)&As[kk][tr * 4];
            float4 a1 = *(const float4*)&As[kk][32 + tr * 4];
            ulonglong2 b0 = *(const ulonglong2*)(const void*)&Bs[kk][tc * 4];
            ulonglong2 b1 = *(const ulonglong2*)(const void*)&Bs[kk][128 + tc * 4];
            unsigned long long ap[8] = {pk2(a0.x, a0.x), pk2(a0.y, a0.y), pk2(a0.z, a0.z),
                                        pk2(a0.w, a0.w), pk2(a1.x, a1.x), pk2(a1.y, a1.y),
                                        pk2(a1.z, a1.z), pk2(a1.w, a1.w)};
            unsigned long long bv[4] = {b0.x, b0.y, b1.x, b1.y};
#pragma unroll
            for (int i = 0; i < 8; i++)
#pragma unroll
                for (int j = 0; j < 4; j++) fma2(accp[i][j], ap[i], bv[j]);
        }
        __syncthreads();
    }

    float acc[8][8];
#pragma unroll
    for (int i = 0; i < 8; i++)
#pragma unroll
        for (int j2 = 0; j2 < 4; j2++) {
            float2 u = upk2(accp[i][j2]);
            acc[i][2 * j2 + 0] = u.x;
            acc[i][2 * j2 + 1] = u.y;
        }

#pragma unroll
    for (int i = 0; i < 8; i++) {
        const int row = n0 + tr * 4 + (i & 3) + ((i >> 2) << 5);
        if (MODE == 2) {
            *(float4*)&g_vmat[row * 256 + tc * 4] =
                make_float4(acc[i][0], acc[i][1], acc[i][2], acc[i][3]);
            *(float4*)&g_vmat[row * 256 + 128 + tc * 4] =
                make_float4(acc[i][4], acc[i][5], acc[i][6], acc[i][7]);
        } else {
            float s = 0.f, ss = 0.f;
#pragma unroll
            for (int j = 0; j < 8; j++) { s += acc[i][j]; ss += acc[i][j] * acc[i][j]; }
#pragma unroll
            for (int o = 16; o > 0; o >>= 1) {
                s  += __shfl_xor_sync(0xffffffffu, s, o);
                ss += __shfl_xor_sync(0xffffffffu, ss, o);
            }
            const float mean = s * (1.0f / 256.0f);
            const float var  = (ss - 256.0f * mean * mean) * (1.0f / 255.0f);
            if (MODE == 0) {
                if (tc == 0) { g_qm[row] = mean; g_qv[row] = var; }
                *(float4*)&g_qc[row * 256 + tc * 4] =
                    make_float4(acc[i][0] - mean, acc[i][1] - mean, acc[i][2] - mean,
                                acc[i][3] - mean);
                *(float4*)&g_qc[row * 256 + 128 + tc * 4] =
                    make_float4(acc[i][4] - mean, acc[i][5] - mean, acc[i][6] - mean,
                                acc[i][7] - mean);
            } else {   // MODE 1: k -> centered transposed
                if (tc == 0) { g_km[row] = mean; g_kv[row] = var; }
#pragma unroll
                for (int j = 0; j < 8; j++) {
                    const int col = tc * 4 + (j & 3) + ((j >> 2) << 7);
                    g_kcT[col * 1024 + row] = acc[i][j] - mean;
                }
            }
        }
    }
}

// =================================================================================
// ssim: S[N, M];  cov = qc @ kc^T / 255, then SSIM rational map.
// Tiles 128x128, BK=32, 256 threads, 8x8 micro (rows tr*4+i/+64, cols tc*4+j/+64)
// =================================================================================
__global__ __launch_bounds__(256, 2) void ssim_kernel() {
    __shared__ float As[32][132];   // As[kk][n]
    __shared__ float Bs[32][132];   // Bs[kk][m]

    const int tid = threadIdx.x;
    const int n0 = blockIdx.y << 7;
    const int m0 = blockIdx.x << 7;
    const int tr = tid >> 4;   // 0..15
    const int tc = tid & 15;   // 0..15

    unsigned long long accp[8][4];
#pragma unroll
    for (int i = 0; i < 8; i++)
#pragma unroll
        for (int j = 0; j < 4; j++) accp[i][j] = 0ull;

    for (int k0 = 0; k0 < 256; k0 += 32) {
#pragma unroll
        for (int it = 0; it < 4; it++) {   // A = g_qc rows (transpose)
            int fid = tid + (it << 8);
            int r = fid >> 3;
            int c = (fid & 7) << 2;
            float4 v = *(const float4*)&g_qc[(n0 + r) * 256 + k0 + c];
            As[c + 0][r] = v.x; As[c + 1][r] = v.y; As[c + 2][r] = v.z; As[c + 3][r] = v.w;
        }
#pragma unroll
        for (int it = 0; it < 4; it++) {   // B = g_kcT (already [F, M], direct copy)
            int fid = tid + (it << 8);
            int rr = fid >> 5;
            int cc = (fid & 31) << 2;
            *(float4*)&Bs[rr][cc] = *(const float4*)&g_kcT[(k0 + rr) * 1024 + m0 + cc];
        }
        __syncthreads();
#pragma unroll
        for (int kk = 0; kk < 32; kk++) {
            float4 a0 = *(const float4*)&As[kk][tr * 4];
            float4 a1 = *(const float4*)&As[kk][64 + tr * 4];
            ulonglong2 b0 = *(const ulonglong2*)(const void*)&Bs[kk][tc * 4];
            ulonglong2 b1 = *(const ulonglong2*)(const void*)&Bs[kk][64 + tc * 4];
            unsigned long long ap[8] = {pk2(a0.x, a0.x), pk2(a0.y, a0.y), pk2(a0.z, a0.z),
                                        pk2(a0.w, a0.w), pk2(a1.x, a1.x), pk2(a1.y, a1.y),
                                        pk2(a1.z, a1.z), pk2(a1.w, a1.w)};
            unsigned long long bv[4] = {b0.x, b0.y, b1.x, b1.y};
#pragma unroll
            for (int i = 0; i < 8; i++)
#pragma unroll
                for (int j = 0; j < 4; j++) fma2(accp[i][j], ap[i], bv[j]);
        }
        __syncthreads();
    }

    float acc[8][8];
#pragma unroll
    for (int i = 0; i < 8; i++)
#pragma unroll
        for (int j2 = 0; j2 < 4; j2++) {
            float2 u = upk2(accp[i][j2]);
            acc[i][2 * j2 + 0] = u.x;
            acc[i][2 * j2 + 1] = u.y;
        }

    const float C1f = 0.01f, C2f = 0.03f, EPSf = 1e-8f, INV255 = 1.0f / 255.0f;

    float qm[8], qv[8], km[8], kv[8];
#pragma unroll
    for (int i = 0; i < 8; i++) {
        const int row = n0 + tr * 4 + (i & 3) + ((i >> 2) << 6);
        qm[i] = g_qm[row];
        qv[i] = g_qv[row];
    }
#pragma unroll
    for (int j = 0; j < 8; j++) {
        const int col = m0 + tc * 4 + (j & 3) + ((j >> 2) << 6);
        km[j] = g_km[col];
        kv[j] = g_kv[col];
    }

#pragma unroll
    for (int i = 0; i < 8; i++) {
        const int row = n0 + tr * 4 + (i & 3) + ((i >> 2) << 6);
        float r[8];
#pragma unroll
        for (int j = 0; j < 8; j++) {
            const float cov = acc[i][j] * INV255;
            const float num = (2.0f * qm[i] * km[j] + C1f) * (2.0f * cov + C2f);
            const float den =
                (qm[i] * qm[i] + km[j] * km[j] + C1f) * (qv[i] + kv[j] + C2f) + EPSf;
            r[j] = num / den;
        }
        *(float4*)&g_S[(size_t)row * 1024 + m0 + tc * 4] =
            make_float4(r[0], r[1], r[2], r[3]);
        *(float4*)&g_S[(size_t)row * 1024 + m0 + 64 + tc * 4] =
            make_float4(r[4], r[5], r[6], r[7]);
    }
}

// =================================================================================
// softmax over M=1024, in place on g_S. One warp per row.
// =================================================================================
__global__ __launch_bounds__(256) void softmax_kernel() {
    const int row  = (blockIdx.x << 3) + (threadIdx.x >> 5);
    const int lane = threadIdx.x & 31;
    float* Sr = &g_S[(size_t)row << 10];

    float v[32];
    float mx = -3.0e38f;
#pragma unroll
    for (int c = 0; c < 8; c++) {
        float4 t = *(const float4*)&Sr[((c << 5) + lane) << 2];
        v[c * 4 + 0] = t.x; v[c * 4 + 1] = t.y; v[c * 4 + 2] = t.z; v[c * 4 + 3] = t.w;
        mx = fmaxf(mx, fmaxf(fmaxf(t.x, t.y), fmaxf(t.z, t.w)));
    }
#pragma unroll
    for (int o = 16; o > 0; o >>= 1) mx = fmaxf(mx, __shfl_xor_sync(0xffffffffu, mx, o));

    float sum = 0.f;
#pragma unroll
    for (int e = 0; e < 32; e++) {
        v[e] = __expf(v[e] - mx);
        sum += v[e];
    }
#pragma unroll
    for (int o = 16; o > 0; o >>= 1) sum += __shfl_xor_sync(0xffffffffu, sum, o);
    const float inv = 1.0f / sum;

#pragma unroll
    for (int c = 0; c < 8; c++) {
        *(float4*)&Sr[((c << 5) + lane) << 2] = make_float4(
            v[c * 4 + 0] * inv, v[c * 4 + 1] * inv, v[c * 4 + 2] * inv, v[c * 4 + 3] * inv);
    }
}

// =================================================================================
// out = att @ v :  [N,1024] x [1024,256] -> d_out.  Tiles 128x128, BK=32.
// =================================================================================
__global__ __launch_bounds__(256, 2) void out_kernel(float* __restrict__ out) {
    __shared__ float As[32][132];   // As[kk][n]   (att)
    __shared__ float Bs[32][132];   // Bs[kk][j]   (v)

    const int tid = threadIdx.x;
    const int n0 = blockIdx.y << 7;
    const int j0 = blockIdx.x << 7;
    const int tr = tid >> 4;
    const int tc = tid & 15;

    unsigned long long accp[8][4];
#pragma unroll
    for (int i = 0; i < 8; i++)
#pragma unroll
        for (int j = 0; j < 4; j++) accp[i][j] = 0ull;

    for (int k0 = 0; k0 < 1024; k0 += 32) {
#pragma unroll
        for (int it = 0; it < 4; it++) {   // A = att rows (transpose)
            int fid = tid + (it << 8);
            int r = fid >> 3;
            int c = (fid & 7) << 2;
            float4 v = *(const float4*)&g_S[(size_t)(n0 + r) * 1024 + k0 + c];
            As[c + 0][r] = v.x; As[c + 1][r] = v.y; As[c + 2][r] = v.z; As[c + 3][r] = v.w;
        }
#pragma unroll
        for (int it = 0; it < 4; it++) {   // B = v rows (direct)
            int fid = tid + (it << 8);
            int rr = fid >> 5;
            int cc = (fid & 31) << 2;
            *(float4*)&Bs[rr][cc] = *(const float4*)&g_vmat[(k0 + rr) * 256 + j0 + cc];
        }
        __syncthreads();
#pragma unroll
        for (int kk = 0; kk < 32; kk++) {
            float4 a0 = *(const float4*)&As[kk][tr * 4];
            float4 a1 = *(const float4*)&As[kk][64 + tr * 4];
            ulonglong2 b0 = *(const ulonglong2*)(const void*)&Bs[kk][tc * 4];
            ulonglong2 b1 = *(const ulonglong2*)(const void*)&Bs[kk][64 + tc * 4];
            unsigned long long ap[8] = {pk2(a0.x, a0.x), pk2(a0.y, a0.y), pk2(a0.z, a0.z),
                                        pk2(a0.w, a0.w), pk2(a1.x, a1.x), pk2(a1.y, a1.y),
                                        pk2(a1.z, a1.z), pk2(a1.w, a1.w)};
            unsigned long long bv[4] = {b0.x, b0.y, b1.x, b1.y};
#pragma unroll
            for (int i = 0; i < 8; i++)
#pragma unroll
                for (int j = 0; j < 4; j++) fma2(accp[i][j], ap[i], bv[j]);
        }
        __syncthreads();
    }

#pragma unroll
    for (int i = 0; i < 8; i++) {
        const int row = n0 + tr * 4 + (i & 3) + ((i >> 2) << 6);
        float2 u0 = upk2(accp[i][0]);
        float2 u1 = upk2(accp[i][1]);
        float2 u2 = upk2(accp[i][2]);
        float2 u3 = upk2(accp[i][3]);
        *(float4*)&out[row * 256 + j0 + tc * 4] = make_float4(u0.x, u0.y, u1.x, u1.y);
        *(float4*)&out[row * 256 + j0 + 64 + tc * 4] = make_float4(u2.x, u2.y, u3.x, u3.y);
    }
}

// =================================================================================
extern "C" void kernel_launch(void* const* d_in, const int* in_sizes, int n_in,
                              void* d_out, int out_size) {
    (void)in_sizes; (void)n_in; (void)out_size;
    const float* x   = (const float*)d_in[0];   // [8192, 8, 256] -> [65536, 256]
    const float* mem = (const float*)d_in[1];   // [1024, 16, 16] -> [1024, 256]
    const float* Wq  = (const float*)d_in[2];   // [256, 256]
    const float* Wk  = (const float*)d_in[3];
    const float* Wv  = (const float*)d_in[4];
    float* out = (float*)d_out;

    rowgemm_kernel<1><<<16, 256>>>(mem, Wk);        // k -> centered kcT + km/kv
    rowgemm_kernel<2><<<16, 256>>>(mem, Wv);        // v
    rowgemm_kernel<0><<<1024, 256>>>(x, Wq);        // q -> centered qc + qm/qv
    ssim_kernel<<<dim3(8, 512), 256>>>();           // S = ssim(q, k)
    softmax_kernel<<<8192, 256>>>();                // S = softmax(S) in place
    out_kernel<<<dim3(2, 512), 256>>>(out);         // out = att @ v
}

// round 6
// speedup vs baseline: 1.5965x; 1.5965x over previous
#include <cuda_runtime.h>

#define NROWS 65536   // N_TOKENS * BATCH
#define FDIM  256     // HW
#define MDIM  1024    // MEM_DIM

// ---------------- scratch (static device globals; no allocation) ----------------
__device__ float g_qc[NROWS * FDIM];            // centered q, row-major [N, F]   (64 MB)
__device__ float g_qm[NROWS];
__device__ float g_qv[NROWS];
__device__ float g_kcT[FDIM * MDIM];            // centered k, TRANSPOSED [F, M]  (1 MB)
__device__ float g_vmat[MDIM * FDIM];           // v, row-major [M, F]            (1 MB)
__device__ float g_km[MDIM];
__device__ float g_kv[MDIM];
__device__ float g_S[(size_t)NROWS * MDIM];     // ssim / att scores [N, M]       (256 MB)

// ---------------- packed f32x2 helpers (full-rate FP32 on sm_103a) --------------
__device__ __forceinline__ unsigned long long pk2(float lo, float hi) {
    unsigned long long r;
    asm("mov.b64 %0, {%1, %2};" : "=l"(r) : "f"(lo), "f"(hi));
    return r;
}
__device__ __forceinline__ void fma2(unsigned long long& d, unsigned long long a,
                                     unsigned long long b) {
    asm("fma.rn.f32x2 %0, %1, %2, %0;" : "+l"(d) : "l"(a), "l"(b));
}
__device__ __forceinline__ float2 upk2(unsigned long long v) {
    float2 r;
    asm("mov.b64 {%0, %1}, %2;" : "=f"(r.x), "=f"(r.y) : "l"(v));
    return r;
}

// =================================================================================
// rowgemm: C[64 x 256] = A_tile @ W^T   (W is [256,256] row-major, C[n,j]=sum A[n,f]W[j,f])
// MODE 0: q     -> row stats (mean/var), write centered rows to g_qc, g_qm/g_qv
// MODE 1: k     -> row stats, write centered TRANSPOSED to g_kcT, g_km/g_kv
// MODE 2: v     -> plain row-major store to g_vmat
// 256 threads, micro-tile 8x8 per thread (rows: tr*4+i / +32, cols: tc*4+j / +128)
// =================================================================================
template <int MODE>
__global__ __launch_bounds__(256, 2) void rowgemm_kernel(const float* __restrict__ A,
                                                         const float* __restrict__ W) {
    __shared__ float As[16][68];    // As[kk][row]
    __shared__ float Bs[16][260];   // Bs[kk][col]

    const int tid = threadIdx.x;
    const int n0  = blockIdx.x * 64;
    const int tr  = tid >> 5;   // 0..7   (warp id; all lanes of a warp share rows)
    const int tc  = tid & 31;   // 0..31

    unsigned long long accp[8][4];
#pragma unroll
    for (int i = 0; i < 8; i++)
#pragma unroll
        for (int j = 0; j < 4; j++) accp[i][j] = 0ull;

    for (int k0 = 0; k0 < 256; k0 += 16) {
        {   // A tile 64x16 (transpose into smem)
            int r = tid >> 2;
            int c = (tid & 3) << 2;
            float4 v = *(const float4*)&A[(n0 + r) * 256 + k0 + c];
            As[c + 0][r] = v.x; As[c + 1][r] = v.y; As[c + 2][r] = v.z; As[c + 3][r] = v.w;
        }
#pragma unroll
        for (int it = 0; it < 4; it++) {   // W tile 256x16 (transpose into smem)
            int fid = tid + (it << 8);
            int j = fid >> 2;
            int c = (fid & 3) << 2;
            float4 v = *(const float4*)&W[j * 256 + k0 + c];
            Bs[c + 0][j] = v.x; Bs[c + 1][j] = v.y; Bs[c + 2][j] = v.z; Bs[c + 3][j] = v.w;
        }
        __syncthreads();
#pragma unroll
        for (int kk = 0; kk < 16; kk++) {
            float4 a0 = *(const float4*)&As[kk][tr * 4];
            float4 a1 = *(const float4*)&As[kk][32 + tr * 4];
            ulonglong2 b0 = *(const ulonglong2*)(const void*)&Bs[kk][tc * 4];
            ulonglong2 b1 = *(const ulonglong2*)(const void*)&Bs[kk][128 + tc * 4];
            unsigned long long ap[8] = {pk2(a0.x, a0.x), pk2(a0.y, a0.y), pk2(a0.z, a0.z),
                                        pk2(a0.w, a0.w), pk2(a1.x, a1.x), pk2(a1.y, a1.y),
                                        pk2(a1.z, a1.z), pk2(a1.w, a1.w)};
            unsigned long long bv[4] = {b0.x, b0.y, b1.x, b1.y};
#pragma unroll
            for (int i = 0; i < 8; i++)
#pragma unroll
                for (int j = 0; j < 4; j++) fma2(accp[i][j], ap[i], bv[j]);
        }
        __syncthreads();
    }

    float acc[8][8];
#pragma unroll
    for (int i = 0; i < 8; i++)
#pragma unroll
        for (int j2 = 0; j2 < 4; j2++) {
            float2 u = upk2(accp[i][j2]);
            acc[i][2 * j2 + 0] = u.x;
            acc[i][2 * j2 + 1] = u.y;
        }

#pragma unroll
    for (int i = 0; i < 8; i++) {
        const int row = n0 + tr * 4 + (i & 3) + ((i >> 2) << 5);
        if (MODE == 2) {
            *(float4*)&g_vmat[row * 256 + tc * 4] =
                make_float4(acc[i][0], acc[i][1], acc[i][2], acc[i][3]);
            *(float4*)&g_vmat[row * 256 + 128 + tc * 4] =
                make_float4(acc[i][4], acc[i][5], acc[i][6], acc[i][7]);
        } else {
            float s = 0.f, ss = 0.f;
#pragma unroll
            for (int j = 0; j < 8; j++) { s += acc[i][j]; ss += acc[i][j] * acc[i][j]; }
#pragma unroll
            for (int o = 16; o > 0; o >>= 1) {
                s  += __shfl_xor_sync(0xffffffffu, s, o);
                ss += __shfl_xor_sync(0xffffffffu, ss, o);
            }
            const float mean = s * (1.0f / 256.0f);
            const float var  = (ss - 256.0f * mean * mean) * (1.0f / 255.0f);
            if (MODE == 0) {
                if (tc == 0) { g_qm[row] = mean; g_qv[row] = var; }
                *(float4*)&g_qc[row * 256 + tc * 4] =
                    make_float4(acc[i][0] - mean, acc[i][1] - mean, acc[i][2] - mean,
                                acc[i][3] - mean);
                *(float4*)&g_qc[row * 256 + 128 + tc * 4] =
                    make_float4(acc[i][4] - mean, acc[i][5] - mean, acc[i][6] - mean,
                                acc[i][7] - mean);
            } else {   // MODE 1: k -> centered transposed
                if (tc == 0) { g_km[row] = mean; g_kv[row] = var; }
#pragma unroll
                for (int j = 0; j < 8; j++) {
                    const int col = tc * 4 + (j & 3) + ((j >> 2) << 7);
                    g_kcT[col * 1024 + row] = acc[i][j] - mean;
                }
            }
        }
    }
}

// =================================================================================
// ssim: S[N, M];  cov = qc @ kc^T / 255, then SSIM rational map.
// Tiles 128x128, BK=32, 256 threads, 8x8 micro (rows tr*4+i/+64, cols tc*4+j/+64)
// =================================================================================
__global__ __launch_bounds__(256, 2) void ssim_kernel() {
    __shared__ float As[32][132];   // As[kk][n]
    __shared__ float Bs[32][132];   // Bs[kk][m]

    const int tid = threadIdx.x;
    const int n0 = blockIdx.y << 7;
    const int m0 = blockIdx.x << 7;
    const int tr = tid >> 4;   // 0..15
    const int tc = tid & 15;   // 0..15

    unsigned long long accp[8][4];
#pragma unroll
    for (int i = 0; i < 8; i++)
#pragma unroll
        for (int j = 0; j < 4; j++) accp[i][j] = 0ull;

    for (int k0 = 0; k0 < 256; k0 += 32) {
#pragma unroll
        for (int it = 0; it < 4; it++) {   // A = g_qc rows (transpose)
            int fid = tid + (it << 8);
            int r = fid >> 3;
            int c = (fid & 7) << 2;
            float4 v = *(const float4*)&g_qc[(n0 + r) * 256 + k0 + c];
            As[c + 0][r] = v.x; As[c + 1][r] = v.y; As[c + 2][r] = v.z; As[c + 3][r] = v.w;
        }
#pragma unroll
        for (int it = 0; it < 4; it++) {   // B = g_kcT (already [F, M], direct copy)
            int fid = tid + (it << 8);
            int rr = fid >> 5;
            int cc = (fid & 31) << 2;
            *(float4*)&Bs[rr][cc] = *(const float4*)&g_kcT[(k0 + rr) * 1024 + m0 + cc];
        }
        __syncthreads();
#pragma unroll
        for (int kk = 0; kk < 32; kk++) {
            float4 a0 = *(const float4*)&As[kk][tr * 4];
            float4 a1 = *(const float4*)&As[kk][64 + tr * 4];
            ulonglong2 b0 = *(const ulonglong2*)(const void*)&Bs[kk][tc * 4];
            ulonglong2 b1 = *(const ulonglong2*)(const void*)&Bs[kk][64 + tc * 4];
            unsigned long long ap[8] = {pk2(a0.x, a0.x), pk2(a0.y, a0.y), pk2(a0.z, a0.z),
                                        pk2(a0.w, a0.w), pk2(a1.x, a1.x), pk2(a1.y, a1.y),
                                        pk2(a1.z, a1.z), pk2(a1.w, a1.w)};
            unsigned long long bv[4] = {b0.x, b0.y, b1.x, b1.y};
#pragma unroll
            for (int i = 0; i < 8; i++)
#pragma unroll
                for (int j = 0; j < 4; j++) fma2(accp[i][j], ap[i], bv[j]);
        }
        __syncthreads();
    }

    float acc[8][8];
#pragma unroll
    for (int i = 0; i < 8; i++)
#pragma unroll
        for (int j2 = 0; j2 < 4; j2++) {
            float2 u = upk2(accp[i][j2]);
            acc[i][2 * j2 + 0] = u.x;
            acc[i][2 * j2 + 1] = u.y;
        }

    const float C1f = 0.01f, C2f = 0.03f, EPSf = 1e-8f, INV255 = 1.0f / 255.0f;

    float qm[8], qv[8], km[8], kv[8];
#pragma unroll
    for (int i = 0; i < 8; i++) {
        const int row = n0 + tr * 4 + (i & 3) + ((i >> 2) << 6);
        qm[i] = g_qm[row];
        qv[i] = g_qv[row];
    }
#pragma unroll
    for (int j = 0; j < 8; j++) {
        const int col = m0 + tc * 4 + (j & 3) + ((j >> 2) << 6);
        km[j] = g_km[col];
        kv[j] = g_kv[col];
    }

#pragma unroll
    for (int i = 0; i < 8; i++) {
        const int row = n0 + tr * 4 + (i & 3) + ((i >> 2) << 6);
        float r[8];
#pragma unroll
        for (int j = 0; j < 8; j++) {
            const float cov = acc[i][j] * INV255;
            const float num = (2.0f * qm[i] * km[j] + C1f) * (2.0f * cov + C2f);
            const float den =
                (qm[i] * qm[i] + km[j] * km[j] + C1f) * (qv[i] + kv[j] + C2f) + EPSf;
            r[j] = num / den;
        }
        *(float4*)&g_S[(size_t)row * 1024 + m0 + tc * 4] =
            make_float4(r[0], r[1], r[2], r[3]);
        *(float4*)&g_S[(size_t)row * 1024 + m0 + 64 + tc * 4] =
            make_float4(r[4], r[5], r[6], r[7]);
    }
}

// =================================================================================
// softmax over M=1024, in place on g_S. One warp per row.
// =================================================================================
__global__ __launch_bounds__(256) void softmax_kernel() {
    const int row  = (blockIdx.x << 3) + (threadIdx.x >> 5);
    const int lane = threadIdx.x & 31;
    float* Sr = &g_S[(size_t)row << 10];

    float v[32];
    float mx = -3.0e38f;
#pragma unroll
    for (int c = 0; c < 8; c++) {
        float4 t = *(const float4*)&Sr[((c << 5) + lane) << 2];
        v[c * 4 + 0] = t.x; v[c * 4 + 1] = t.y; v[c * 4 + 2] = t.z; v[c * 4 + 3] = t.w;
        mx = fmaxf(mx, fmaxf(fmaxf(t.x, t.y), fmaxf(t.z, t.w)));
    }
#pragma unroll
    for (int o = 16; o > 0; o >>= 1) mx = fmaxf(mx, __shfl_xor_sync(0xffffffffu, mx, o));

    float sum = 0.f;
#pragma unroll
    for (int e = 0; e < 32; e++) {
        v[e] = __expf(v[e] - mx);
        sum += v[e];
    }
#pragma unroll
    for (int o = 16; o > 0; o >>= 1) sum += __shfl_xor_sync(0xffffffffu, sum, o);
    const float inv = 1.0f / sum;

#pragma unroll
    for (int c = 0; c < 8; c++) {
        *(float4*)&Sr[((c << 5) + lane) << 2] = make_float4(
            v[c * 4 + 0] * inv, v[c * 4 + 1] * inv, v[c * 4 + 2] * inv, v[c * 4 + 3] * inv);
    }
}

// =================================================================================
// out = att @ v :  [N,1024] x [1024,256] -> d_out.  Tiles 128x128, BK=32.
// =================================================================================
__global__ __launch_bounds__(256, 2) void out_kernel(float* __restrict__ out) {
    __shared__ float As[32][132];   // As[kk][n]   (att)
    __shared__ float Bs[32][132];   // Bs[kk][j]   (v)

    const int tid = threadIdx.x;
    const int n0 = blockIdx.y << 7;
    const int j0 = blockIdx.x << 7;
    const int tr = tid >> 4;
    const int tc = tid & 15;

    unsigned long long accp[8][4];
#pragma unroll
    for (int i = 0; i < 8; i++)
#pragma unroll
        for (int j = 0; j < 4; j++) accp[i][j] = 0ull;

    for (int k0 = 0; k0 < 1024; k0 += 32) {
#pragma unroll
        for (int it = 0; it < 4; it++) {   // A = att rows (transpose)
            int fid = tid + (it << 8);
            int r = fid >> 3;
            int c = (fid & 7) << 2;
            float4 v = *(const float4*)&g_S[(size_t)(n0 + r) * 1024 + k0 + c];
            As[c + 0][r] = v.x; As[c + 1][r] = v.y; As[c + 2][r] = v.z; As[c + 3][r] = v.w;
        }
#pragma unroll
        for (int it = 0; it < 4; it++) {   // B = v rows (direct)
            int fid = tid + (it << 8);
            int rr = fid >> 5;
            int cc = (fid & 31) << 2;
            *(float4*)&Bs[rr][cc] = *(const float4*)&g_vmat[(k0 + rr) * 256 + j0 + cc];
        }
        __syncthreads();
#pragma unroll
        for (int kk = 0; kk < 32; kk++) {
            float4 a0 = *(const float4*)&As[kk][tr * 4];
            float4 a1 = *(const float4*)&As[kk][64 + tr * 4];
            ulonglong2 b0 = *(const ulonglong2*)(const void*)&Bs[kk][tc * 4];
            ulonglong2 b1 = *(const ulonglong2*)(const void*)&Bs[kk][64 + tc * 4];
            unsigned long long ap[8] = {pk2(a0.x, a0.x), pk2(a0.y, a0.y), pk2(a0.z, a0.z),
                                        pk2(a0.w, a0.w), pk2(a1.x, a1.x), pk2(a1.y, a1.y),
                                        pk2(a1.z, a1.z), pk2(a1.w, a1.w)};
            unsigned long long bv[4] = {b0.x, b0.y, b1.x, b1.y};
#pragma unroll
            for (int i = 0; i < 8; i++)
#pragma unroll
                for (int j = 0; j < 4; j++) fma2(accp[i][j], ap[i], bv[j]);
        }
        __syncthreads();
    }

#pragma unroll
    for (int i = 0; i < 8; i++) {
        const int row = n0 + tr * 4 + (i & 3) + ((i >> 2) << 6);
        float2 u0 = upk2(accp[i][0]);
        float2 u1 = upk2(accp[i][1]);
        float2 u2 = upk2(accp[i][2]);
        float2 u3 = upk2(accp[i][3]);
        *(float4*)&out[row * 256 + j0 + tc * 4] = make_float4(u0.x, u0.y, u1.x, u1.y);
        *(float4*)&out[row * 256 + j0 + 64 + tc * 4] = make_float4(u2.x, u2.y, u3.x, u3.y);
    }
}

// =================================================================================
extern "C" void kernel_launch(void* const* d_in, const int* in_sizes, int n_in,
                              void* d_out, int out_size) {
    (void)in_sizes; (void)n_in; (void)out_size;
    const float* x   = (const float*)d_in[0];   // [8192, 8, 256] -> [65536, 256]
    const float* mem = (const float*)d_in[1];   // [1024, 16, 16] -> [1024, 256]
    const float* Wq  = (const float*)d_in[2];   // [256, 256]
    const float* Wk  = (const float*)d_in[3];
    const float* Wv  = (const float*)d_in[4];
    float* out = (float*)d_out;

    rowgemm_kernel<1><<<16, 256>>>(mem, Wk);        // k -> centered kcT + km/kv
    rowgemm_kernel<2><<<16, 256>>>(mem, Wv);        // v
    rowgemm_kernel<0><<<1024, 256>>>(x, Wq);        // q -> centered qc + qm/qv
    ssim_kernel<<<dim3(8, 512), 256>>>();           // S = ssim(q, k)
    softmax_kernel<<<8192, 256>>>();                // S = softmax(S) in place
    out_kernel<<<dim3(2, 512), 256>>>(out);         // out = att @ v
}